// round 15
// baseline (speedup 1.0000x reference)
#include <cuda_runtime.h>
#include <stdint.h>
#include <math.h>

#define HN 64
#define GN 256
#define NTHREADS 256

__device__ __forceinline__ uint32_t rotl32(uint32_t x, uint32_t r){ return (x<<r)|(x>>(32u-r)); }

// Threefry-2x32, 20 rounds, JAX key schedule.
__device__ __forceinline__ void tf2x32(uint32_t k0, uint32_t k1, uint32_t c0, uint32_t c1,
                                       uint32_t &o0, uint32_t &o1){
  uint32_t ks2 = k0 ^ k1 ^ 0x1BD11BDAu;
  uint32_t x0 = c0 + k0;
  uint32_t x1 = c1 + k1;
  x0+=x1; x1=rotl32(x1,13); x1^=x0;
  x0+=x1; x1=rotl32(x1,15); x1^=x0;
  x0+=x1; x1=rotl32(x1,26); x1^=x0;
  x0+=x1; x1=rotl32(x1, 6); x1^=x0;
  x0+=k1;  x1+=ks2+1u;
  x0+=x1; x1=rotl32(x1,17); x1^=x0;
  x0+=x1; x1=rotl32(x1,29); x1^=x0;
  x0+=x1; x1=rotl32(x1,16); x1^=x0;
  x0+=x1; x1=rotl32(x1,24); x1^=x0;
  x0+=ks2; x1+=k0+2u;
  x0+=x1; x1=rotl32(x1,13); x1^=x0;
  x0+=x1; x1=rotl32(x1,15); x1^=x0;
  x0+=x1; x1=rotl32(x1,26); x1^=x0;
  x0+=x1; x1=rotl32(x1, 6); x1^=x0;
  x0+=k0;  x1+=k1+3u;
  x0+=x1; x1=rotl32(x1,17); x1^=x0;
  x0+=x1; x1=rotl32(x1,29); x1^=x0;
  x0+=x1; x1=rotl32(x1,16); x1^=x0;
  x0+=x1; x1=rotl32(x1,24); x1^=x0;
  x0+=k1;  x1+=ks2+4u;
  x0+=x1; x1=rotl32(x1,13); x1^=x0;
  x0+=x1; x1=rotl32(x1,15); x1^=x0;
  x0+=x1; x1=rotl32(x1,26); x1^=x0;
  x0+=x1; x1=rotl32(x1, 6); x1^=x0;
  x0+=ks2; x1+=k0+5u;
  o0=x0; o1=x1;
}

// JAX partitionable uniform -> gumbel (off hot path)
__device__ __forceinline__ float bits2gumbel(uint32_t b){
  float u = __uint_as_float((b>>9)|0x3f800000u) - 1.0f;
  const float tiny = 1.17549435e-38f;
  u = fmaxf(tiny, u + tiny);
  return -logf(-logf(u));
}

__device__ __forceinline__ float sig_fast(float x){
  return __fdividef(1.0f, 1.0f + __expf(-x));
}
__device__ __forceinline__ float tanh_fast(float x){
  return 1.0f - __fdividef(2.0f, 1.0f + __expf(2.0f*x));
}

// warp-collective sample over n<=6 categories; lane<n holds lgt, else -1e30.
// 8-wide butterflies cover all valid lanes (winner lane < 8); idx broadcast
// from lane 0. Returns idx (uniform). Writes action/entropy/logprob outputs.
__device__ __forceinline__ int sample_warp(int lane, int n, float lgt,
                                           const float* gum_row,
                                           float* out, int step, int out_size){
  float gv = gum_row[lane & 7];                 // in-bounds (stride-8 row)
  float gum = (lane<n) ? (lgt + gv) : -1e30f;
  int idx = lane;
  #pragma unroll
  for (int off=4;off;off>>=1){
    float g2=__shfl_xor_sync(0xffffffffu,gum,off);
    int   i2=__shfl_xor_sync(0xffffffffu,idx,off);
    if (g2>gum || (g2==gum && i2<idx)){ gum=g2; idx=i2; }
  }
  idx = __shfl_sync(0xffffffffu, idx, 0);       // lane-0 group holds true argmax
  float mx = lgt;
  #pragma unroll
  for (int off=4;off;off>>=1) mx = fmaxf(mx, __shfl_xor_sync(0xffffffffu,mx,off));
  float e = (lane<n) ? __expf(lgt-mx) : 0.f;
  float se = e;
  float t  = e*lgt;     // e==0 for invalid lanes -> 0 contribution
  #pragma unroll
  for (int off=4;off;off>>=1){
    se += __shfl_xor_sync(0xffffffffu,se,off);
    t  += __shfl_xor_sync(0xffffffffu,t, off);
  }
  float lse = __logf(se);
  if (lane==0){
    float ent = mx + lse - __fdividef(t, se);
    if (step    < out_size) out[step]    = (float)idx;
    if (40+step < out_size) out[40+step] = ent;
  }
  if (lane==idx && 80+step < out_size) out[80+step] = lgt - mx - lse;
  return idx;
}

__global__ void __launch_bounds__(NTHREADS, 1)
controller_kernel(const float* __restrict__ ef, const float* __restrict__ eo,
                  const float* __restrict__ wih_g, const float* __restrict__ whh_g,
                  const float* __restrict__ wprev_g, const float* __restrict__ wcurr_g,
                  const float* __restrict__ wout_g, const float* __restrict__ wops_g,
                  const float* __restrict__ bops_g, const float* __restrict__ abias_g,
                  float* __restrict__ out, int out_size)
{
  __shared__ float s_wprevT[HN*HN];   // transposed: [k*64 + j]
  __shared__ float s_wcurrT[HN*HN];
  __shared__ float s_wops[5*HN];
  __shared__ float s_wout[HN];
  __shared__ float s_bops[8];
  __shared__ float s_abias[8];
  __shared__ float s_h[HN];
  __shared__ float s_c[HN];
  __shared__ float s_g[GN];
  __shared__ float s_lg[HN];
  __shared__ float s_prevfc[6*HN];    // prev_fc[6] never read
  __shared__ float s_gum[40*8];       // stride-8 rows, masked reads in-bounds
  __shared__ float s_dot[8];
  __shared__ float s_pxh[4*NTHREADS]; // prev_h[2..5] @ w_ih.T
  __shared__ float s_pxo[5*NTHREADS]; // embed_ops   @ w_ih.T (const)
  __shared__ int   s_xsel;            // -1: embed_first, -2: zero, 0..3: pxh row, 8..12: pxo row

  const int tid  = threadIdx.x;
  const int lane = tid & 31;
  const int warp = tid >> 5;
  const int gate = tid >> 6;   // 0:i 1:f 2:g 3:o

  // ---- cooperative loads ----
  for (int i=tid;i<HN;i+=NTHREADS) s_wout[i]=wout_g[i];
  for (int i=tid;i<5*HN;i+=NTHREADS) s_wops[i]=wops_g[i];
  if (tid<8){
    s_bops[tid]  = (tid<5)? bops_g[tid]  : 0.f;
    s_abias[tid] = (tid<5)? abias_g[tid] : 0.f;
    s_dot[tid]   = 0.f;
    if (tid==0) s_xsel = -1;   // first input: embed_first
  }
  for (int i=tid;i<HN*HN;i+=NTHREADS){
    int j=i>>6, k=i&63;
    s_wprevT[k*HN+j]=wprev_g[i];
    s_wcurrT[k*HN+j]=wcurr_g[i];
  }
  // recurrent weight row -> registers (ONLY whh; wih stays in global/L1)
  float whh[HN];
  #pragma unroll
  for (int k=0;k<HN;k++) whh[k]=whh_g[tid*HN+k];

  // constant x-projections through w_ih.T (global reads, init only)
  const float* wih_row = wih_g + tid*HN;
  float r_pxf;
  {
    float a0=0.f,a1=0.f;
    #pragma unroll 4
    for (int k=0;k<HN;k+=2){ a0=fmaf(wih_row[k],ef[k],a0); a1=fmaf(wih_row[k+1],ef[k+1],a1); }
    r_pxf = a0+a1;
  }
  for (int a=0;a<5;a++){
    float a0=0.f,a1=0.f;
    #pragma unroll 4
    for (int k=0;k<HN;k+=2){ a0=fmaf(wih_row[k],eo[a*HN+k],a0); a1=fmaf(wih_row[k+1],eo[a*HN+k+1],a1); }
    s_pxo[a*NTHREADS+tid]=a0+a1;
  }

  // ---- Gumbel table (input-independent; partitionable threefry) ----
  if (tid < 40){
    int r = tid % 20;
    int within = r & 3;
    int nd = 2 + (r>>2);
    int n  = (within<2) ? nd : 5;
    uint32_t k0,k1;
    tf2x32(0u, 42u, 0u, (uint32_t)(tid+1), k0, k1);   // fold_in(key(42), step)
    for (int i=0;i<8;i++){
      if (i<n){
        uint32_t o0,o1; tf2x32(k0,k1, 0u, (uint32_t)i, o0,o1);
        s_gum[tid*8+i] = bits2gumbel(o0 ^ o1);
      } else {
        s_gum[tid*8+i] = 0.f;
      }
    }
  }
  __syncthreads();

  if (tid<HN){ s_h[tid]=0.f; s_c[tid]=0.f; }

  int step = 0;

  auto lstm = [&](){
    __syncthreads();                       // covers prior selector/pxh/h writes
    int sel = s_xsel;
    float px = (sel==-1) ? r_pxf
             : (sel==-2) ? 0.f
             : (sel<8)   ? s_pxh[sel*NTHREADS+tid]
                         : s_pxo[(sel-8)*NTHREADS+tid];
    float a0=0.f,a1=0.f,a2=0.f,a3=0.f;
    #pragma unroll
    for (int k=0;k<HN;k+=4){
      a0 = fmaf(whh[k],   s_h[k],   a0);
      a1 = fmaf(whh[k+1], s_h[k+1], a1);
      a2 = fmaf(whh[k+2], s_h[k+2], a2);
      a3 = fmaf(whh[k+3], s_h[k+3], a3);
    }
    float g = px + (a0+a1)+(a2+a3);
    // gate nonlinearity in parallel across all 256 threads
    s_g[tid] = (gate==2) ? tanh_fast(g) : sig_fast(g);
    __syncthreads();
    if (tid<HN){
      float c = s_g[HN+tid]*s_c[tid] + s_g[tid]*s_g[2*HN+tid];
      s_c[tid]=c;
      s_h[tid]=s_g[3*HN+tid]*tanh_fast(c);
    }
    __syncthreads();
  };

  for (int cell=0; cell<2; cell++){
    // two warm-up LSTM steps (x=embed_first both): prev_fc <- h @ w_index_prev.T
    for (int t=0;t<2;t++){
      lstm();
      if (tid<HN){
        float b0=0.f,b1=0.f,b2=0.f,b3=0.f;
        #pragma unroll
        for (int k=0;k<HN;k+=4){
          b0=fmaf(s_h[k  ], s_wprevT[(k  )*HN+tid], b0);
          b1=fmaf(s_h[k+1], s_wprevT[(k+1)*HN+tid], b1);
          b2=fmaf(s_h[k+2], s_wprevT[(k+2)*HN+tid], b2);
          b3=fmaf(s_h[k+3], s_wprevT[(k+3)*HN+tid], b3);
        }
        s_prevfc[t*HN+tid]=(b0+b1)+(b2+b3);
      }
      // next lstm's entry sync covers these writes
    }
    for (int node=2; node<7; node++){
      // ---- 2 index draws ----
      for (int t=0;t<2;t++){
        lstm();
        if (tid<HN){
          float b0=0.f,b1=0.f,b2=0.f,b3=0.f;
          #pragma unroll
          for (int k=0;k<HN;k+=4){
            b0=fmaf(s_h[k  ], s_wcurrT[(k  )*HN+tid], b0);
            b1=fmaf(s_h[k+1], s_wcurrT[(k+1)*HN+tid], b1);
            b2=fmaf(s_h[k+2], s_wcurrT[(k+2)*HN+tid], b2);
            b3=fmaf(s_h[k+3], s_wcurrT[(k+3)*HN+tid], b3);
          }
          s_lg[tid]=(b0+b1)+(b2+b3);
        }
        __syncthreads();
        if (warp < node){   // q_i = tanh(prev_fc[i]+lg) . w_out
          float v = tanh_fast(s_prevfc[warp*HN+lane]    + s_lg[lane])    * s_wout[lane]
                  + tanh_fast(s_prevfc[warp*HN+lane+32] + s_lg[lane+32]) * s_wout[lane+32];
          #pragma unroll
          for (int off=16;off>0;off>>=1) v += __shfl_xor_sync(0xffffffffu, v, off);
          if (lane==0) s_dot[warp]=v;
        }
        __syncthreads();
        if (warp==0){
          float dv = s_dot[lane & 7];          // masked, in-bounds
          float lgt = (lane<node) ? 1.1f*tanh_fast(dv) : -1e30f;
          int a = sample_warp(lane, node, lgt, &s_gum[step*8], out, step, out_size);
          if (lane==0) s_xsel = (a>=2) ? (a-2) : -2;   // prev_h[0,1] are zero
        }
        step++;
        // next lstm's entry sync covers s_xsel
      }
      // ---- 2 op draws ----
      for (int t=0;t<2;t++){
        lstm();
        if (warp<5){
          float v = s_h[lane]*s_wops[warp*HN+lane] + s_h[lane+32]*s_wops[warp*HN+lane+32];
          #pragma unroll
          for (int off=16;off>0;off>>=1) v += __shfl_xor_sync(0xffffffffu, v, off);
          if (lane==0) s_dot[warp]=v;
        }
        __syncthreads();
        if (warp==0){
          float dv = s_dot[lane & 7];          // masked, in-bounds
          float bv = s_bops[lane & 7];
          float ab = s_abias[lane & 7];
          float lgt = (lane<5) ? fmaf(0.44f, tanh_fast(dv+bv), ab) : -1e30f;
          int a = sample_warp(lane, 5, lgt, &s_gum[step*8], out, step, out_size);
          if (lane==0) s_xsel = 8 + a;
        }
        step++;
        // next lstm's entry sync covers s_xsel
      }
      // ---- node-closing LSTM step ----
      lstm();
      if (node<6){
        if (tid<HN){
          float b0=0.f,b1=0.f,b2=0.f,b3=0.f;
          #pragma unroll
          for (int k=0;k<HN;k+=4){
            b0=fmaf(s_h[k  ], s_wprevT[(k  )*HN+tid], b0);
            b1=fmaf(s_h[k+1], s_wprevT[(k+1)*HN+tid], b1);
            b2=fmaf(s_h[k+2], s_wprevT[(k+2)*HN+tid], b2);
            b3=fmaf(s_h[k+3], s_wprevT[(k+3)*HN+tid], b3);
          }
          s_prevfc[node*HN+tid]=(b0+b1)+(b2+b3);
        }
        // prev_h[node] @ w_ih.T  (wih row from global/L1; 10 occurrences total)
        float a0=0.f,a1=0.f;
        #pragma unroll 8
        for (int k=0;k<HN;k+=2){
          a0=fmaf(wih_row[k],   s_h[k],   a0);
          a1=fmaf(wih_row[k+1], s_h[k+1], a1);
        }
        s_pxh[(node-2)*NTHREADS+tid]=a0+a1;
      }
      if (tid==0) s_xsel = -1;   // x = embed_first
      // next lstm's entry sync covers these writes
    }
  }
}

extern "C" void kernel_launch(void* const* d_in, const int* in_sizes, int n_in,
                              void* d_out, int out_size)
{
  controller_kernel<<<1, NTHREADS>>>(
      (const float*)d_in[0],  // embed_first_w (1,64)
      (const float*)d_in[1],  // embed_ops_w   (5,64)
      (const float*)d_in[2],  // w_ih          (256,64)
      (const float*)d_in[3],  // w_hh          (256,64)
      (const float*)d_in[4],  // w_index_prev  (64,64)
      (const float*)d_in[5],  // w_index_curr  (64,64)
      (const float*)d_in[6],  // w_index_out   (1,64)
      (const float*)d_in[7],  // w_ops         (5,64)
      (const float*)d_in[8],  // b_ops         (5,)
      (const float*)d_in[9],  // additional_bias (5,)
      (float*)d_out, out_size);
}

// round 16
// speedup vs baseline: 3.9689x; 3.9689x over previous
#include <cuda_runtime.h>
#include <stdint.h>
#include <math.h>

#define HN 64
#define GN 256
#define NTHREADS 256

__device__ __forceinline__ uint32_t rotl32(uint32_t x, uint32_t r){ return (x<<r)|(x>>(32u-r)); }

// Threefry-2x32, 20 rounds, JAX key schedule.
__device__ __forceinline__ void tf2x32(uint32_t k0, uint32_t k1, uint32_t c0, uint32_t c1,
                                       uint32_t &o0, uint32_t &o1){
  uint32_t ks2 = k0 ^ k1 ^ 0x1BD11BDAu;
  uint32_t x0 = c0 + k0;
  uint32_t x1 = c1 + k1;
  x0+=x1; x1=rotl32(x1,13); x1^=x0;
  x0+=x1; x1=rotl32(x1,15); x1^=x0;
  x0+=x1; x1=rotl32(x1,26); x1^=x0;
  x0+=x1; x1=rotl32(x1, 6); x1^=x0;
  x0+=k1;  x1+=ks2+1u;
  x0+=x1; x1=rotl32(x1,17); x1^=x0;
  x0+=x1; x1=rotl32(x1,29); x1^=x0;
  x0+=x1; x1=rotl32(x1,16); x1^=x0;
  x0+=x1; x1=rotl32(x1,24); x1^=x0;
  x0+=ks2; x1+=k0+2u;
  x0+=x1; x1=rotl32(x1,13); x1^=x0;
  x0+=x1; x1=rotl32(x1,15); x1^=x0;
  x0+=x1; x1=rotl32(x1,26); x1^=x0;
  x0+=x1; x1=rotl32(x1, 6); x1^=x0;
  x0+=k0;  x1+=k1+3u;
  x0+=x1; x1=rotl32(x1,17); x1^=x0;
  x0+=x1; x1=rotl32(x1,29); x1^=x0;
  x0+=x1; x1=rotl32(x1,16); x1^=x0;
  x0+=x1; x1=rotl32(x1,24); x1^=x0;
  x0+=k1;  x1+=ks2+4u;
  x0+=x1; x1=rotl32(x1,13); x1^=x0;
  x0+=x1; x1=rotl32(x1,15); x1^=x0;
  x0+=x1; x1=rotl32(x1,26); x1^=x0;
  x0+=x1; x1=rotl32(x1, 6); x1^=x0;
  x0+=ks2; x1+=k0+5u;
  o0=x0; o1=x1;
}

// JAX partitionable uniform -> gumbel (off hot path)
__device__ __forceinline__ float bits2gumbel(uint32_t b){
  float u = __uint_as_float((b>>9)|0x3f800000u) - 1.0f;
  const float tiny = 1.17549435e-38f;
  u = fmaxf(tiny, u + tiny);
  return -logf(-logf(u));
}

__device__ __forceinline__ float sig_fast(float x){
  return __fdividef(1.0f, 1.0f + __expf(-x));
}
__device__ __forceinline__ float tanh_fast(float x){
  return 1.0f - __fdividef(2.0f, 1.0f + __expf(2.0f*x));
}

// warp-collective sample over n<=6 categories; lane<n holds lgt, else -1e30.
// 8-wide butterflies cover all valid lanes (winner lane < 8); idx broadcast
// from lane 0. Returns idx (uniform). Writes action/entropy/logprob outputs.
__device__ __forceinline__ int sample_warp(int lane, int n, float lgt,
                                           const float* gum_row,
                                           float* out, int step, int out_size){
  float gv = gum_row[lane & 7];                 // in-bounds (stride-8 row)
  float gum = (lane<n) ? (lgt + gv) : -1e30f;
  int idx = lane;
  #pragma unroll
  for (int off=4;off;off>>=1){
    float g2=__shfl_xor_sync(0xffffffffu,gum,off);
    int   i2=__shfl_xor_sync(0xffffffffu,idx,off);
    if (g2>gum || (g2==gum && i2<idx)){ gum=g2; idx=i2; }
  }
  idx = __shfl_sync(0xffffffffu, idx, 0);       // lane-0 group holds true argmax
  float mx = lgt;
  #pragma unroll
  for (int off=4;off;off>>=1) mx = fmaxf(mx, __shfl_xor_sync(0xffffffffu,mx,off));
  float e = (lane<n) ? __expf(lgt-mx) : 0.f;
  float se = e;
  float t  = e*lgt;     // e==0 for invalid lanes -> 0 contribution
  #pragma unroll
  for (int off=4;off;off>>=1){
    se += __shfl_xor_sync(0xffffffffu,se,off);
    t  += __shfl_xor_sync(0xffffffffu,t, off);
  }
  float lse = __logf(se);
  if (lane==0){
    float ent = mx + lse - __fdividef(t, se);
    if (step    < out_size) out[step]    = (float)idx;
    if (40+step < out_size) out[40+step] = ent;
  }
  if (lane==idx && 80+step < out_size) out[80+step] = lgt - mx - lse;
  return idx;
}

__global__ void __launch_bounds__(NTHREADS, 1)
controller_kernel(const float* __restrict__ ef, const float* __restrict__ eo,
                  const float* __restrict__ wih_g, const float* __restrict__ whh_g,
                  const float* __restrict__ wprev_g, const float* __restrict__ wcurr_g,
                  const float* __restrict__ wout_g, const float* __restrict__ wops_g,
                  const float* __restrict__ bops_g, const float* __restrict__ abias_g,
                  float* __restrict__ out, int out_size)
{
  __shared__ float s_wprevT[HN*HN];   // transposed: [k*64 + j]
  __shared__ float s_wcurrT[HN*HN];
  __shared__ float s_wops[5*HN];
  __shared__ float s_wout[HN];
  __shared__ float s_bops[8];
  __shared__ float s_abias[8];
  __shared__ float s_h[HN];
  __shared__ float s_c[HN];
  __shared__ float s_g[GN];
  __shared__ float s_lg[HN];
  __shared__ float s_prevfc[6*HN];    // prev_fc[6] never read
  __shared__ float s_gum[40*8];       // stride-8 rows, masked reads in-bounds
  __shared__ float s_dot[8];
  __shared__ float s_pxh[4*NTHREADS]; // prev_h[2..5] @ w_ih.T
  __shared__ float s_pxo[5*NTHREADS]; // embed_ops   @ w_ih.T (const)
  __shared__ int   s_xsel;            // -1: embed_first, -2: zero, 0..3: pxh, 8..12: pxo

  const int tid  = threadIdx.x;
  const int lane = tid & 31;
  const int warp = tid >> 5;
  const int gate = tid >> 6;   // 0:i 1:f 2:g 3:o

  // ---- cooperative loads ----
  for (int i=tid;i<HN;i+=NTHREADS) s_wout[i]=wout_g[i];
  for (int i=tid;i<5*HN;i+=NTHREADS) s_wops[i]=wops_g[i];
  if (tid<8){
    s_bops[tid]  = (tid<5)? bops_g[tid]  : 0.f;
    s_abias[tid] = (tid<5)? abias_g[tid] : 0.f;
    s_dot[tid]   = 0.f;
    if (tid==0) s_xsel = -1;   // first input: embed_first
  }
  for (int i=tid;i<HN*HN;i+=NTHREADS){
    int j=i>>6, k=i&63;
    s_wprevT[k*HN+j]=wprev_g[i];
    s_wcurrT[k*HN+j]=wcurr_g[i];
  }
  // LSTM weight rows -> registers. wih is loaded ONCE here (proven-cheap in
  // R8/R14) and used for all projections; it never generates steady-state LDG.
  float wih[HN], whh[HN];
  #pragma unroll
  for (int k=0;k<HN;k++){ wih[k]=wih_g[tid*HN+k]; whh[k]=whh_g[tid*HN+k]; }

  // constant x-projections (register wih . broadcast global vectors)
  float r_pxf;
  {
    float a0=0.f,a1=0.f;
    #pragma unroll 8
    for (int k=0;k<HN;k+=2){ a0=fmaf(wih[k],ef[k],a0); a1=fmaf(wih[k+1],ef[k+1],a1); }
    r_pxf = a0+a1;
  }
  #pragma unroll
  for (int a=0;a<5;a++){
    float a0=0.f,a1=0.f;
    #pragma unroll 8
    for (int k=0;k<HN;k+=2){ a0=fmaf(wih[k],eo[a*HN+k],a0); a1=fmaf(wih[k+1],eo[a*HN+k+1],a1); }
    s_pxo[a*NTHREADS+tid]=a0+a1;
  }

  // ---- Gumbel table (input-independent; partitionable threefry) ----
  if (tid < 40){
    int r = tid % 20;
    int within = r & 3;
    int nd = 2 + (r>>2);
    int n  = (within<2) ? nd : 5;
    uint32_t k0,k1;
    tf2x32(0u, 42u, 0u, (uint32_t)(tid+1), k0, k1);   // fold_in(key(42), step)
    for (int i=0;i<8;i++){
      if (i<n){
        uint32_t o0,o1; tf2x32(k0,k1, 0u, (uint32_t)i, o0,o1);
        s_gum[tid*8+i] = bits2gumbel(o0 ^ o1);
      } else {
        s_gum[tid*8+i] = 0.f;
      }
    }
  }
  __syncthreads();

  if (tid<HN){ s_h[tid]=0.f; s_c[tid]=0.f; }

  int step = 0;

  auto lstm = [&](){
    __syncthreads();                       // covers prior selector/pxh/h writes
    int sel = s_xsel;
    float px = (sel==-1) ? r_pxf
             : (sel==-2) ? 0.f
             : (sel<8)   ? s_pxh[sel*NTHREADS+tid]
                         : s_pxo[(sel-8)*NTHREADS+tid];
    float a0=0.f,a1=0.f,a2=0.f,a3=0.f;
    #pragma unroll
    for (int k=0;k<HN;k+=4){
      a0 = fmaf(whh[k],   s_h[k],   a0);
      a1 = fmaf(whh[k+1], s_h[k+1], a1);
      a2 = fmaf(whh[k+2], s_h[k+2], a2);
      a3 = fmaf(whh[k+3], s_h[k+3], a3);
    }
    float g = px + (a0+a1)+(a2+a3);
    // gate nonlinearity in parallel across all 256 threads
    s_g[tid] = (gate==2) ? tanh_fast(g) : sig_fast(g);
    __syncthreads();
    if (tid<HN){
      float c = s_g[HN+tid]*s_c[tid] + s_g[tid]*s_g[2*HN+tid];
      s_c[tid]=c;
      s_h[tid]=s_g[3*HN+tid]*tanh_fast(c);
    }
    __syncthreads();
  };

  for (int cell=0; cell<2; cell++){
    // two warm-up LSTM steps (x=embed_first both): prev_fc <- h @ w_index_prev.T
    for (int t=0;t<2;t++){
      lstm();
      if (tid<HN){
        float b0=0.f,b1=0.f,b2=0.f,b3=0.f;
        #pragma unroll
        for (int k=0;k<HN;k+=4){
          b0=fmaf(s_h[k  ], s_wprevT[(k  )*HN+tid], b0);
          b1=fmaf(s_h[k+1], s_wprevT[(k+1)*HN+tid], b1);
          b2=fmaf(s_h[k+2], s_wprevT[(k+2)*HN+tid], b2);
          b3=fmaf(s_h[k+3], s_wprevT[(k+3)*HN+tid], b3);
        }
        s_prevfc[t*HN+tid]=(b0+b1)+(b2+b3);
      }
      // next lstm's entry sync covers these writes
    }
    for (int node=2; node<7; node++){
      // ---- 2 index draws ----
      for (int t=0;t<2;t++){
        lstm();
        if (tid<HN){
          float b0=0.f,b1=0.f,b2=0.f,b3=0.f;
          #pragma unroll
          for (int k=0;k<HN;k+=4){
            b0=fmaf(s_h[k  ], s_wcurrT[(k  )*HN+tid], b0);
            b1=fmaf(s_h[k+1], s_wcurrT[(k+1)*HN+tid], b1);
            b2=fmaf(s_h[k+2], s_wcurrT[(k+2)*HN+tid], b2);
            b3=fmaf(s_h[k+3], s_wcurrT[(k+3)*HN+tid], b3);
          }
          s_lg[tid]=(b0+b1)+(b2+b3);
        }
        __syncthreads();
        if (warp < node){   // q_i = tanh(prev_fc[i]+lg) . w_out
          float v = tanh_fast(s_prevfc[warp*HN+lane]    + s_lg[lane])    * s_wout[lane]
                  + tanh_fast(s_prevfc[warp*HN+lane+32] + s_lg[lane+32]) * s_wout[lane+32];
          #pragma unroll
          for (int off=16;off>0;off>>=1) v += __shfl_xor_sync(0xffffffffu, v, off);
          if (lane==0) s_dot[warp]=v;
        }
        __syncthreads();
        if (warp==0){
          float dv = s_dot[lane & 7];          // masked, in-bounds
          float lgt = (lane<node) ? 1.1f*tanh_fast(dv) : -1e30f;
          int a = sample_warp(lane, node, lgt, &s_gum[step*8], out, step, out_size);
          if (lane==0) s_xsel = (a>=2) ? (a-2) : -2;   // prev_h[0,1] are zero
        }
        step++;
        // next lstm's entry sync covers s_xsel
      }
      // ---- 2 op draws ----
      for (int t=0;t<2;t++){
        lstm();
        if (warp<5){
          float v = s_h[lane]*s_wops[warp*HN+lane] + s_h[lane+32]*s_wops[warp*HN+lane+32];
          #pragma unroll
          for (int off=16;off>0;off>>=1) v += __shfl_xor_sync(0xffffffffu, v, off);
          if (lane==0) s_dot[warp]=v;
        }
        __syncthreads();
        if (warp==0){
          float dv = s_dot[lane & 7];          // masked, in-bounds
          float bv = s_bops[lane & 7];
          float ab = s_abias[lane & 7];
          float lgt = (lane<5) ? fmaf(0.44f, tanh_fast(dv+bv), ab) : -1e30f;
          int a = sample_warp(lane, 5, lgt, &s_gum[step*8], out, step, out_size);
          if (lane==0) s_xsel = 8 + a;
        }
        step++;
        // next lstm's entry sync covers s_xsel
      }
      // ---- node-closing LSTM step ----
      lstm();
      if (node<6){
        if (tid<HN){
          float b0=0.f,b1=0.f,b2=0.f,b3=0.f;
          #pragma unroll
          for (int k=0;k<HN;k+=4){
            b0=fmaf(s_h[k  ], s_wprevT[(k  )*HN+tid], b0);
            b1=fmaf(s_h[k+1], s_wprevT[(k+1)*HN+tid], b1);
            b2=fmaf(s_h[k+2], s_wprevT[(k+2)*HN+tid], b2);
            b3=fmaf(s_h[k+3], s_wprevT[(k+3)*HN+tid], b3);
          }
          s_prevfc[node*HN+tid]=(b0+b1)+(b2+b3);
        }
        // prev_h[node] @ w_ih.T  (register wih x smem h; no LDG)
        float a0=0.f,a1=0.f,a2=0.f,a3=0.f;
        #pragma unroll
        for (int k=0;k<HN;k+=4){
          a0 = fmaf(wih[k],   s_h[k],   a0);
          a1 = fmaf(wih[k+1], s_h[k+1], a1);
          a2 = fmaf(wih[k+2], s_h[k+2], a2);
          a3 = fmaf(wih[k+3], s_h[k+3], a3);
        }
        s_pxh[(node-2)*NTHREADS+tid]=(a0+a1)+(a2+a3);
      }
      if (tid==0) s_xsel = -1;   // x = embed_first
      // next lstm's entry sync covers these writes
    }
  }
}

extern "C" void kernel_launch(void* const* d_in, const int* in_sizes, int n_in,
                              void* d_out, int out_size)
{
  controller_kernel<<<1, NTHREADS>>>(
      (const float*)d_in[0],  // embed_first_w (1,64)
      (const float*)d_in[1],  // embed_ops_w   (5,64)
      (const float*)d_in[2],  // w_ih          (256,64)
      (const float*)d_in[3],  // w_hh          (256,64)
      (const float*)d_in[4],  // w_index_prev  (64,64)
      (const float*)d_in[5],  // w_index_curr  (64,64)
      (const float*)d_in[6],  // w_index_out   (1,64)
      (const float*)d_in[7],  // w_ops         (5,64)
      (const float*)d_in[8],  // b_ops         (5,)
      (const float*)d_in[9],  // additional_bias (5,)
      (float*)d_out, out_size);
}

// round 17
// speedup vs baseline: 4.1958x; 1.0572x over previous
#include <cuda_runtime.h>
#include <stdint.h>
#include <math.h>

#define HN 64
#define GN 256
#define NTHREADS 256

__device__ __forceinline__ uint32_t rotl32(uint32_t x, uint32_t r){ return (x<<r)|(x>>(32u-r)); }

// Threefry-2x32, 20 rounds, JAX key schedule.
__device__ __forceinline__ void tf2x32(uint32_t k0, uint32_t k1, uint32_t c0, uint32_t c1,
                                       uint32_t &o0, uint32_t &o1){
  uint32_t ks2 = k0 ^ k1 ^ 0x1BD11BDAu;
  uint32_t x0 = c0 + k0;
  uint32_t x1 = c1 + k1;
  x0+=x1; x1=rotl32(x1,13); x1^=x0;
  x0+=x1; x1=rotl32(x1,15); x1^=x0;
  x0+=x1; x1=rotl32(x1,26); x1^=x0;
  x0+=x1; x1=rotl32(x1, 6); x1^=x0;
  x0+=k1;  x1+=ks2+1u;
  x0+=x1; x1=rotl32(x1,17); x1^=x0;
  x0+=x1; x1=rotl32(x1,29); x1^=x0;
  x0+=x1; x1=rotl32(x1,16); x1^=x0;
  x0+=x1; x1=rotl32(x1,24); x1^=x0;
  x0+=ks2; x1+=k0+2u;
  x0+=x1; x1=rotl32(x1,13); x1^=x0;
  x0+=x1; x1=rotl32(x1,15); x1^=x0;
  x0+=x1; x1=rotl32(x1,26); x1^=x0;
  x0+=x1; x1=rotl32(x1, 6); x1^=x0;
  x0+=k0;  x1+=k1+3u;
  x0+=x1; x1=rotl32(x1,17); x1^=x0;
  x0+=x1; x1=rotl32(x1,29); x1^=x0;
  x0+=x1; x1=rotl32(x1,16); x1^=x0;
  x0+=x1; x1=rotl32(x1,24); x1^=x0;
  x0+=k1;  x1+=ks2+4u;
  x0+=x1; x1=rotl32(x1,13); x1^=x0;
  x0+=x1; x1=rotl32(x1,15); x1^=x0;
  x0+=x1; x1=rotl32(x1,26); x1^=x0;
  x0+=x1; x1=rotl32(x1, 6); x1^=x0;
  x0+=ks2; x1+=k0+5u;
  o0=x0; o1=x1;
}

// JAX partitionable uniform -> gumbel (off hot path)
__device__ __forceinline__ float bits2gumbel(uint32_t b){
  float u = __uint_as_float((b>>9)|0x3f800000u) - 1.0f;
  const float tiny = 1.17549435e-38f;
  u = fmaxf(tiny, u + tiny);
  return -logf(-logf(u));
}

__device__ __forceinline__ float sig_fast(float x){
  return __fdividef(1.0f, 1.0f + __expf(-x));
}
__device__ __forceinline__ float tanh_fast(float x){
  return 1.0f - __fdividef(2.0f, 1.0f + __expf(2.0f*x));
}

// warp-collective sample over n<=6 categories; lane<n holds lgt, else -1e30.
// 8-wide butterflies cover all valid lanes (winner lane < 8); idx broadcast
// from lane 0. Returns idx (uniform). Writes action/entropy/logprob outputs.
__device__ __forceinline__ int sample_warp(int lane, int n, float lgt,
                                           const float* gum_row,
                                           float* out, int step, int out_size){
  float gv = gum_row[lane & 7];                 // in-bounds (stride-8 row)
  float gum = (lane<n) ? (lgt + gv) : -1e30f;
  int idx = lane;
  #pragma unroll
  for (int off=4;off;off>>=1){
    float g2=__shfl_xor_sync(0xffffffffu,gum,off);
    int   i2=__shfl_xor_sync(0xffffffffu,idx,off);
    if (g2>gum || (g2==gum && i2<idx)){ gum=g2; idx=i2; }
  }
  idx = __shfl_sync(0xffffffffu, idx, 0);       // lane-0 group holds true argmax
  float mx = lgt;
  #pragma unroll
  for (int off=4;off;off>>=1) mx = fmaxf(mx, __shfl_xor_sync(0xffffffffu,mx,off));
  float e = (lane<n) ? __expf(lgt-mx) : 0.f;
  float se = e;
  float t  = e*lgt;     // e==0 for invalid lanes -> 0 contribution
  #pragma unroll
  for (int off=4;off;off>>=1){
    se += __shfl_xor_sync(0xffffffffu,se,off);
    t  += __shfl_xor_sync(0xffffffffu,t, off);
  }
  float lse = __logf(se);
  if (lane==0){
    float ent = mx + lse - __fdividef(t, se);
    if (step    < out_size) out[step]    = (float)idx;
    if (40+step < out_size) out[40+step] = ent;
  }
  if (lane==idx && 80+step < out_size) out[80+step] = lgt - mx - lse;
  return idx;
}

__global__ void __launch_bounds__(NTHREADS, 1)
controller_kernel(const float* __restrict__ ef, const float* __restrict__ eo,
                  const float* __restrict__ wih_g, const float* __restrict__ whh_g,
                  const float* __restrict__ wprev_g, const float* __restrict__ wcurr_g,
                  const float* __restrict__ wout_g, const float* __restrict__ wops_g,
                  const float* __restrict__ bops_g, const float* __restrict__ abias_g,
                  float* __restrict__ out, int out_size)
{
  __shared__ float s_wprevT[HN*HN];   // transposed: [k*64 + j]
  __shared__ float s_wcurrT[HN*HN];
  __shared__ float s_wops[5*HN];
  __shared__ float s_wout[HN];
  __shared__ float s_bops[8];
  __shared__ float s_abias[8];
  __shared__ float s_h[HN];
  __shared__ float s_c[HN];
  __shared__ float s_g[GN];
  __shared__ float s_lg[HN];
  __shared__ float s_prevfc[6*HN];    // prev_fc[6] never read
  __shared__ float s_gum[40*8];       // stride-8 rows, masked reads in-bounds
  __shared__ float s_dot[8];
  __shared__ float s_pxh[4*NTHREADS]; // prev_h[2..5] @ w_ih.T (scratch at init)
  __shared__ float s_pxo[5*NTHREADS]; // embed_ops   @ w_ih.T (const)
  __shared__ int   s_xsel;            // -1: embed_first, -2: zero, 0..3: pxh, 8..12: pxo

  const int tid  = threadIdx.x;
  const int lane = tid & 31;
  const int warp = tid >> 5;
  const int gate = tid >> 6;   // 0:i 1:f 2:g 3:o

  // ---- cooperative loads ----
  for (int i=tid;i<HN;i+=NTHREADS) s_wout[i]=wout_g[i];
  for (int i=tid;i<5*HN;i+=NTHREADS) s_wops[i]=wops_g[i];
  if (tid<8){
    s_bops[tid]  = (tid<5)? bops_g[tid]  : 0.f;
    s_abias[tid] = (tid<5)? abias_g[tid] : 0.f;
    s_dot[tid]   = 0.f;
    if (tid==0) s_xsel = -1;   // first input: embed_first
  }
  for (int i=tid;i<HN*HN;i+=NTHREADS){
    int j=i>>6, k=i&63;
    s_wprevT[k*HN+j]=wprev_g[i];
    s_wcurrT[k*HN+j]=wcurr_g[i];
  }
  // stage ef/eo into smem scratch (s_pxh is free until first node-closing)
  for (int i=tid;i<5*HN;i+=NTHREADS) s_pxh[i]=eo[i];
  if (tid<HN) s_pxh[5*HN+tid]=ef[tid];

  // LSTM weight rows -> registers (loaded once; steady state has zero LDG)
  float wih[HN], whh[HN];
  #pragma unroll
  for (int k=0;k<HN;k++){ wih[k]=wih_g[tid*HN+k]; whh[k]=whh_g[tid*HN+k]; }
  __syncthreads();

  // constant x-projections: register wih . broadcast smem vectors (tiny live range)
  float r_pxf;
  {
    const float* v = &s_pxh[5*HN];
    float a0=0.f,a1=0.f;
    for (int k=0;k<HN;k+=2){ a0=fmaf(wih[k],v[k],a0); a1=fmaf(wih[k+1],v[k+1],a1); }
    r_pxf = a0+a1;
  }
  for (int a=0;a<5;a++){
    const float* v = &s_pxh[a*HN];
    float a0=0.f,a1=0.f;
    for (int k=0;k<HN;k+=2){ a0=fmaf(wih[k],v[k],a0); a1=fmaf(wih[k+1],v[k+1],a1); }
    s_pxo[a*NTHREADS+tid]=a0+a1;
  }

  // ---- Gumbel table (input-independent; partitionable threefry) ----
  if (tid < 40){
    int r = tid % 20;
    int within = r & 3;
    int nd = 2 + (r>>2);
    int n  = (within<2) ? nd : 5;
    uint32_t k0,k1;
    tf2x32(0u, 42u, 0u, (uint32_t)(tid+1), k0, k1);   // fold_in(key(42), step)
    for (int i=0;i<8;i++){
      if (i<n){
        uint32_t o0,o1; tf2x32(k0,k1, 0u, (uint32_t)i, o0,o1);
        s_gum[tid*8+i] = bits2gumbel(o0 ^ o1);
      } else {
        s_gum[tid*8+i] = 0.f;
      }
    }
  }
  __syncthreads();

  if (tid<HN){ s_h[tid]=0.f; s_c[tid]=0.f; }

  int step = 0;

  auto lstm = [&](){
    __syncthreads();                       // covers prior selector/pxh/h writes
    int sel = s_xsel;
    float px = (sel==-1) ? r_pxf
             : (sel==-2) ? 0.f
             : (sel<8)   ? s_pxh[sel*NTHREADS+tid]
                         : s_pxo[(sel-8)*NTHREADS+tid];
    float a0=0.f,a1=0.f,a2=0.f,a3=0.f;
    #pragma unroll
    for (int k=0;k<HN;k+=4){
      a0 = fmaf(whh[k],   s_h[k],   a0);
      a1 = fmaf(whh[k+1], s_h[k+1], a1);
      a2 = fmaf(whh[k+2], s_h[k+2], a2);
      a3 = fmaf(whh[k+3], s_h[k+3], a3);
    }
    float g = px + (a0+a1)+(a2+a3);
    // gate nonlinearity in parallel across all 256 threads
    s_g[tid] = (gate==2) ? tanh_fast(g) : sig_fast(g);
    __syncthreads();
    if (tid<HN){
      float c = s_g[HN+tid]*s_c[tid] + s_g[tid]*s_g[2*HN+tid];
      s_c[tid]=c;
      s_h[tid]=s_g[3*HN+tid]*tanh_fast(c);
    }
    __syncthreads();
  };

  for (int cell=0; cell<2; cell++){
    // two warm-up LSTM steps (x=embed_first both): prev_fc <- h @ w_index_prev.T
    for (int t=0;t<2;t++){
      lstm();
      if (tid<HN){
        float b0=0.f,b1=0.f,b2=0.f,b3=0.f;
        #pragma unroll
        for (int k=0;k<HN;k+=4){
          b0=fmaf(s_h[k  ], s_wprevT[(k  )*HN+tid], b0);
          b1=fmaf(s_h[k+1], s_wprevT[(k+1)*HN+tid], b1);
          b2=fmaf(s_h[k+2], s_wprevT[(k+2)*HN+tid], b2);
          b3=fmaf(s_h[k+3], s_wprevT[(k+3)*HN+tid], b3);
        }
        s_prevfc[t*HN+tid]=(b0+b1)+(b2+b3);
      }
      // next lstm's entry sync covers these writes
    }
    for (int node=2; node<7; node++){
      // ---- 2 index draws ----
      for (int t=0;t<2;t++){
        lstm();
        if (tid<HN){
          float b0=0.f,b1=0.f,b2=0.f,b3=0.f;
          #pragma unroll
          for (int k=0;k<HN;k+=4){
            b0=fmaf(s_h[k  ], s_wcurrT[(k  )*HN+tid], b0);
            b1=fmaf(s_h[k+1], s_wcurrT[(k+1)*HN+tid], b1);
            b2=fmaf(s_h[k+2], s_wcurrT[(k+2)*HN+tid], b2);
            b3=fmaf(s_h[k+3], s_wcurrT[(k+3)*HN+tid], b3);
          }
          s_lg[tid]=(b0+b1)+(b2+b3);
        }
        __syncthreads();
        if (warp < node){   // q_i = tanh(prev_fc[i]+lg) . w_out
          float v = tanh_fast(s_prevfc[warp*HN+lane]    + s_lg[lane])    * s_wout[lane]
                  + tanh_fast(s_prevfc[warp*HN+lane+32] + s_lg[lane+32]) * s_wout[lane+32];
          #pragma unroll
          for (int off=16;off>0;off>>=1) v += __shfl_xor_sync(0xffffffffu, v, off);
          if (lane==0) s_dot[warp]=v;
        }
        __syncthreads();
        if (warp==0){
          float dv = s_dot[lane & 7];          // masked, in-bounds
          float lgt = (lane<node) ? 1.1f*tanh_fast(dv) : -1e30f;
          int a = sample_warp(lane, node, lgt, &s_gum[step*8], out, step, out_size);
          if (lane==0) s_xsel = (a>=2) ? (a-2) : -2;   // prev_h[0,1] are zero
        }
        step++;
        // next lstm's entry sync covers s_xsel
      }
      // ---- 2 op draws ----
      for (int t=0;t<2;t++){
        lstm();
        if (warp<5){
          float v = s_h[lane]*s_wops[warp*HN+lane] + s_h[lane+32]*s_wops[warp*HN+lane+32];
          #pragma unroll
          for (int off=16;off>0;off>>=1) v += __shfl_xor_sync(0xffffffffu, v, off);
          if (lane==0) s_dot[warp]=v;
        }
        __syncthreads();
        if (warp==0){
          float dv = s_dot[lane & 7];          // masked, in-bounds
          float bv = s_bops[lane & 7];
          float ab = s_abias[lane & 7];
          float lgt = (lane<5) ? fmaf(0.44f, tanh_fast(dv+bv), ab) : -1e30f;
          int a = sample_warp(lane, 5, lgt, &s_gum[step*8], out, step, out_size);
          if (lane==0) s_xsel = 8 + a;
        }
        step++;
        // next lstm's entry sync covers s_xsel
      }
      // ---- node-closing LSTM step ----
      lstm();
      if (node<6){
        if (tid<HN){
          float b0=0.f,b1=0.f,b2=0.f,b3=0.f;
          #pragma unroll
          for (int k=0;k<HN;k+=4){
            b0=fmaf(s_h[k  ], s_wprevT[(k  )*HN+tid], b0);
            b1=fmaf(s_h[k+1], s_wprevT[(k+1)*HN+tid], b1);
            b2=fmaf(s_h[k+2], s_wprevT[(k+2)*HN+tid], b2);
            b3=fmaf(s_h[k+3], s_wprevT[(k+3)*HN+tid], b3);
          }
          s_prevfc[node*HN+tid]=(b0+b1)+(b2+b3);
        }
        // prev_h[node] @ w_ih.T  (register wih x smem h; no LDG)
        float a0=0.f,a1=0.f,a2=0.f,a3=0.f;
        #pragma unroll
        for (int k=0;k<HN;k+=4){
          a0 = fmaf(wih[k],   s_h[k],   a0);
          a1 = fmaf(wih[k+1], s_h[k+1], a1);
          a2 = fmaf(wih[k+2], s_h[k+2], a2);
          a3 = fmaf(wih[k+3], s_h[k+3], a3);
        }
        s_pxh[(node-2)*NTHREADS+tid]=(a0+a1)+(a2+a3);
      }
      if (tid==0) s_xsel = -1;   // x = embed_first
      // next lstm's entry sync covers these writes
    }
  }
}

extern "C" void kernel_launch(void* const* d_in, const int* in_sizes, int n_in,
                              void* d_out, int out_size)
{
  controller_kernel<<<1, NTHREADS>>>(
      (const float*)d_in[0],  // embed_first_w (1,64)
      (const float*)d_in[1],  // embed_ops_w   (5,64)
      (const float*)d_in[2],  // w_ih          (256,64)
      (const float*)d_in[3],  // w_hh          (256,64)
      (const float*)d_in[4],  // w_index_prev  (64,64)
      (const float*)d_in[5],  // w_index_curr  (64,64)
      (const float*)d_in[6],  // w_index_out   (1,64)
      (const float*)d_in[7],  // w_ops         (5,64)
      (const float*)d_in[8],  // b_ops         (5,)
      (const float*)d_in[9],  // additional_bias (5,)
      (float*)d_out, out_size);
}